// round 3
// baseline (speedup 1.0000x reference)
#include <cuda_runtime.h>
#include <math_constants.h>

#define BATCH 2
#define NPTS 1024
#define KNN 8
#define TI 4
#define THREADS 256

// FACTOR_A = 180 / (15 * pi) = 12/pi
#define FACTOR_A 3.8197186342054885f
#define EPS 1e-6f

__global__ __launch_bounds__(THREADS)
void gse_kernel(const float* __restrict__ points,
                const float* __restrict__ normals,
                float* __restrict__ cat_out,   // [B,N,N,3]
                float* __restrict__ a_out)     // [B,N,N,K]
{
    __shared__ float px[NPTS], py[NPTS], pz[NPTS];
    __shared__ float nxs[NPTS], nys[NPTS], nzs[NPTS];
    __shared__ float nnorm[NPTS], sq[NPTS], sq_strict[NPTS];
    __shared__ float dsel[NPTS];
    __shared__ float redv[THREADS / 32];
    __shared__ int   redi[THREADS / 32];
    __shared__ int   knn_idx[KNN];
    __shared__ float rkv[KNN][3];

    const int b   = blockIdx.x >> 8;            // N/TI = 256 blocks per batch
    const int i0  = (blockIdx.x & 255) * TI;
    const int tid = threadIdx.x;

    // ---- load batch points/normals into SoA smem ----
    const float* pb = points  + (size_t)b * NPTS * 3;
    const float* nb = normals + (size_t)b * NPTS * 3;
    for (int idx = tid; idx < NPTS * 3; idx += THREADS) {
        int j = idx / 3;
        int c = idx - j * 3;
        float pv = pb[idx];
        float nv = nb[idx];
        if (c == 0)      { px[j] = pv; nxs[j] = nv; }
        else if (c == 1) { py[j] = pv; nys[j] = nv; }
        else             { pz[j] = pv; nzs[j] = nv; }
    }
    __syncthreads();
    for (int j = tid; j < NPTS; j += THREADS) {
        float x = px[j], y = py[j], z = pz[j];
        sq[j] = x * x + y * y + z * z;   // fast version for phase C
        // strict emulation of jnp.sum(p*p, -1): ((x*x) + (y*y)) + (z*z), each rounded
        sq_strict[j] = __fadd_rn(__fadd_rn(__fmul_rn(x, x), __fmul_rn(y, y)),
                                 __fmul_rn(z, z));
        nnorm[j] = sqrtf(nxs[j] * nxs[j] + nys[j] * nys[j] + nzs[j] * nzs[j]);
    }
    __syncthreads();

    for (int ii = 0; ii < TI; ii++) {
        const int i = i0 + ii;
        const float pix = px[i], piy = py[i], piz = pz[i];
        const float sqi  = sq[i];
        const float sqis = sq_strict[i];

        // ---- phase A: selection distances, strict fp32 rounding (no fast-math) ----
        for (int j = tid; j < NPTS; j += THREADS) {
            float dot = __fadd_rn(__fadd_rn(__fmul_rn(pix, px[j]),
                                            __fmul_rn(piy, py[j])),
                                  __fmul_rn(piz, pz[j]));
            float d2 = __fsub_rn(__fadd_rn(sqis, sq_strict[j]),
                                 __fmul_rn(2.0f, dot));
            float dist = __fsqrt_rn(fmaxf(d2, 0.0f));
            dsel[j] = (j == i) ? CUDART_INF_F : dist;  // drop self (== idx[...,0])
        }
        __syncthreads();

        // ---- phase B: 8 rounds of parallel argmin (ascending dist, tie -> smaller j) ----
        for (int k = 0; k < KNN; k++) {
            float best = CUDART_INF_F;
            int   bidx = NPTS;
            for (int j = tid; j < NPTS; j += THREADS) {
                float v = dsel[j];
                if (v < best || (v == best && j < bidx)) { best = v; bidx = j; }
            }
            #pragma unroll
            for (int off = 16; off > 0; off >>= 1) {
                float ov = __shfl_down_sync(0xffffffffu, best, off);
                int   oi = __shfl_down_sync(0xffffffffu, bidx, off);
                if (ov < best || (ov == best && oi < bidx)) { best = ov; bidx = oi; }
            }
            if ((tid & 31) == 0) { redv[tid >> 5] = best; redi[tid >> 5] = bidx; }
            __syncthreads();
            if (tid == 0) {
                float bb = redv[0]; int bi = redi[0];
                #pragma unroll
                for (int w = 1; w < THREADS / 32; w++) {
                    if (redv[w] < bb || (redv[w] == bb && redi[w] < bi)) {
                        bb = redv[w]; bi = redi[w];
                    }
                }
                knn_idx[k]  = bi;
                dsel[bi]    = CUDART_INF_F;
            }
            __syncthreads();
        }

        if (tid < KNN) {
            int jn = knn_idx[tid];
            rkv[tid][0] = px[jn] - pix;
            rkv[tid][1] = py[jn] - piy;
            rkv[tid][2] = pz[jn] - piz;
        }
        __syncthreads();

        // ref vectors to registers
        float rkx[KNN], rky[KNN], rkz[KNN];
        #pragma unroll
        for (int k = 0; k < KNN; k++) {
            rkx[k] = rkv[k][0];
            rky[k] = rkv[k][1];
            rkz[k] = rkv[k][2];
        }

        const float nix = nxs[i], niy = nys[i], niz = nzs[i];
        const float nni = nnorm[i];
        float* catRow = cat_out + ((size_t)(b * NPTS + i)) * NPTS * 3;
        float* aRow   = a_out   + ((size_t)(b * NPTS + i)) * NPTS * KNN;

        // ---- phase C: full pair row ----
        for (int j = tid; j < NPTS; j += THREADS) {
            float pjx = px[j], pjy = py[j], pjz = pz[j];
            float dx = pjx - pix, dy = pjy - piy, dz = pjz - piz;  // lianxian[b,i,j]
            float l  = sqrtf(dx * dx + dy * dy + dz * dz);         // l_norm

            // dist_map uses the sq-formula (not |d|)
            float d2f  = sqi + sq[j] - 2.0f * (pix * pjx + piy * pjy + piz * pjz);
            float dist = sqrtf(fmaxf(d2f, 0.0f));

            // rad[i,j] and rad[j,i]
            float doti = nix * dx + niy * dy + niz * dz;
            float ci   = doti / (nni * l + EPS);
            ci = fminf(fmaxf(ci, -1.0f), 1.0f);
            float radij = acosf(ci);

            float nnj  = nnorm[j];
            float dotj = -(nxs[j] * dx + nys[j] * dy + nzs[j] * dz);  // n_j . (p_i - p_j)
            float cj   = dotj / (nnj * l + EPS);
            cj = fminf(fmaxf(cj, -1.0f), 1.0f);
            float radji = acosf(cj);

            float angle = fabsf(radij - radji);

            // seta
            float nnd = nix * nxs[j] + niy * nys[j] + niz * nzs[j];
            float x   = nnd / (nni * nnj);
            if (x != x) x = 0.0f;
            x = fminf(fmaxf(x, -1.0f), 1.0f);
            float seta = acosf(x);

            catRow[j * 3 + 0] = dist * (1.0f / 0.2f);
            catRow[j * 3 + 1] = seta;
            catRow[j * 3 + 2] = angle;

            float av[KNN];
            #pragma unroll
            for (int k = 0; k < KNN; k++) {
                float cx = rky[k] * dz - rkz[k] * dy;
                float cy = rkz[k] * dx - rkx[k] * dz;
                float cz = rkx[k] * dy - rky[k] * dx;
                float s  = sqrtf(cx * cx + cy * cy + cz * cz);
                float c  = rkx[k] * dx + rky[k] * dy + rkz[k] * dz;
                av[k] = atan2f(s, c) * FACTOR_A;
            }
            // j == i diagonal: anc_vec is exactly +0; XLA's sum-reduce starts at +0,
            // so cos_vals = +0 and arctan2(+0,+0) = 0 for EVERY k, regardless of the
            // sign pattern of ref_vec (our fma dot can yield -0 -> atan2 = pi = wrong 12.0).
            if (j == i) {
                #pragma unroll
                for (int k = 0; k < KNN; k++) av[k] = 0.0f;
            }
            float4* ap = reinterpret_cast<float4*>(aRow + (size_t)j * KNN);
            ap[0] = make_float4(av[0], av[1], av[2], av[3]);
            ap[1] = make_float4(av[4], av[5], av[6], av[7]);
        }
        __syncthreads();  // dsel reused next row
    }
}

extern "C" void kernel_launch(void* const* d_in, const int* in_sizes, int n_in,
                              void* d_out, int out_size)
{
    const float* points  = (const float*)d_in[0];
    const float* normals = (const float*)d_in[1];
    (void)in_sizes; (void)n_in; (void)out_size;

    float* out  = (float*)d_out;
    float* cat  = out;                                   // [B,N,N,3]
    float* aidx = out + (size_t)BATCH * NPTS * NPTS * 3; // [B,N,N,K]

    gse_kernel<<<BATCH * (NPTS / TI), THREADS>>>(points, normals, cat, aidx);
}

// round 4
// speedup vs baseline: 1.6061x; 1.6061x over previous
#include <cuda_runtime.h>
#include <math_constants.h>

#define BATCH 2
#define NPTS 1024
#define KNN 8
#define TI 4
#define THREADS 256

// FACTOR_A = 180 / (15 * pi) = 12/pi
#define FACTOR_A 3.8197186342054885f
#define EPS 1e-6f

// Branchless acos, Abramowitz-Stegun 4.4.45 (|err| <= 6.7e-5 rad).
__device__ __forceinline__ float facos(float x) {
    float ax = fminf(fabsf(x), 1.0f);
    float p = fmaf(ax, -0.0187293f, 0.0742610f);
    p = fmaf(ax, p, -0.2121144f);
    p = fmaf(ax, p, 1.5707288f);
    float s = sqrtf(1.0f - ax) * p;
    return (x >= 0.0f) ? s : (CUDART_PI_F - s);
}

// FACTOR_A * acos(x); note pi * FACTOR_A == 12 exactly.
__device__ __forceinline__ float facos12(float x) {
    float ax = fminf(fabsf(x), 1.0f);
    float p = fmaf(ax, -0.0187293f * FACTOR_A, 0.0742610f * FACTOR_A);
    p = fmaf(ax, p, -0.2121144f * FACTOR_A);
    p = fmaf(ax, p, 1.5707288f * FACTOR_A);
    float s = sqrtf(1.0f - ax) * p;
    return (x >= 0.0f) ? s : (12.0f - s);
}

__global__ __launch_bounds__(THREADS)
void gse_kernel(const float* __restrict__ points,
                const float* __restrict__ normals,
                float* __restrict__ cat_out,   // [B,N,N,3]
                float* __restrict__ a_out)     // [B,N,N,K]
{
    __shared__ float4 P[NPTS];    // x, y, z, |p|^2 (strict rounding)
    __shared__ float4 Nn[NPTS];   // nx, ny, nz, |n|
    __shared__ float  rnn[NPTS];  // 1 / |n|
    __shared__ float  dsel[NPTS];
    __shared__ float  redv[THREADS / 32];
    __shared__ int    redi[THREADS / 32];
    __shared__ int    knn_idx[KNN];
    __shared__ float  rkv[KNN][3];  // normalized ref vectors

    const int b   = blockIdx.x >> 8;            // N/TI = 256 blocks per batch
    const int i0  = (blockIdx.x & 255) * TI;
    const int tid = threadIdx.x;

    // ---- load batch points/normals into smem (float4 SoA-of-structs) ----
    const float* pb = points  + (size_t)b * NPTS * 3;
    const float* nb = normals + (size_t)b * NPTS * 3;
    for (int j = tid; j < NPTS; j += THREADS) {
        float x = pb[3 * j], y = pb[3 * j + 1], z = pb[3 * j + 2];
        // strict emulation of jnp.sum(p*p,-1): ((x*x)+(y*y))+(z*z), each rounded
        float sqs = __fadd_rn(__fadd_rn(__fmul_rn(x, x), __fmul_rn(y, y)),
                              __fmul_rn(z, z));
        P[j] = make_float4(x, y, z, sqs);
        float nx = nb[3 * j], ny = nb[3 * j + 1], nz = nb[3 * j + 2];
        float nn = sqrtf(nx * nx + ny * ny + nz * nz);
        Nn[j]  = make_float4(nx, ny, nz, nn);
        rnn[j] = __fdividef(1.0f, nn);
    }
    __syncthreads();

    for (int ii = 0; ii < TI; ii++) {
        const int i = i0 + ii;
        const float4 Pi = P[i];
        const float pix = Pi.x, piy = Pi.y, piz = Pi.z, sqis = Pi.w;

        // ---- phase A: selection distances, strict fp32 rounding (matches jax) ----
        for (int j = tid; j < NPTS; j += THREADS) {
            float4 Pj = P[j];
            float dot = __fadd_rn(__fadd_rn(__fmul_rn(pix, Pj.x),
                                            __fmul_rn(piy, Pj.y)),
                                  __fmul_rn(piz, Pj.z));
            float d2 = __fsub_rn(__fadd_rn(sqis, Pj.w), __fmul_rn(2.0f, dot));
            float dist = __fsqrt_rn(fmaxf(d2, 0.0f));
            dsel[j] = (j == i) ? CUDART_INF_F : dist;  // drop self (== idx[...,0])
        }
        __syncthreads();

        // ---- phase B: 8 rounds of parallel argmin (ascending, tie -> smaller j) ----
        for (int k = 0; k < KNN; k++) {
            float best = CUDART_INF_F;
            int   bidx = NPTS;
            for (int j = tid; j < NPTS; j += THREADS) {
                float v = dsel[j];
                if (v < best || (v == best && j < bidx)) { best = v; bidx = j; }
            }
            #pragma unroll
            for (int off = 16; off > 0; off >>= 1) {
                float ov = __shfl_down_sync(0xffffffffu, best, off);
                int   oi = __shfl_down_sync(0xffffffffu, bidx, off);
                if (ov < best || (ov == best && oi < bidx)) { best = ov; bidx = oi; }
            }
            if ((tid & 31) == 0) { redv[tid >> 5] = best; redi[tid >> 5] = bidx; }
            __syncthreads();
            if (tid == 0) {
                float bb = redv[0]; int bi = redi[0];
                #pragma unroll
                for (int w = 1; w < THREADS / 32; w++) {
                    if (redv[w] < bb || (redv[w] == bb && redi[w] < bi)) {
                        bb = redv[w]; bi = redi[w];
                    }
                }
                knn_idx[k] = bi;
                dsel[bi]   = CUDART_INF_F;
            }
            __syncthreads();
        }

        if (tid < KNN) {
            int jn = knn_idx[tid];
            float rx = P[jn].x - pix, ry = P[jn].y - piy, rz = P[jn].z - piz;
            float rinv = __fdividef(1.0f, sqrtf(rx * rx + ry * ry + rz * rz));
            rkv[tid][0] = rx * rinv;
            rkv[tid][1] = ry * rinv;
            rkv[tid][2] = rz * rinv;
        }
        __syncthreads();

        float rkx[KNN], rky[KNN], rkz[KNN];
        #pragma unroll
        for (int k = 0; k < KNN; k++) {
            rkx[k] = rkv[k][0];
            rky[k] = rkv[k][1];
            rkz[k] = rkv[k][2];
        }

        const float4 Ni = Nn[i];
        const float nix = Ni.x, niy = Ni.y, niz = Ni.z, nni = Ni.w;
        const float rnni = rnn[i];
        float* catRow = cat_out + ((size_t)(b * NPTS + i)) * NPTS * 3;
        float* aRow   = a_out   + ((size_t)(b * NPTS + i)) * NPTS * KNN;

        // ---- phase C: full pair row ----
        for (int j = tid; j < NPTS; j += THREADS) {
            float4 Pj = P[j];
            float4 Nj = Nn[j];
            float dx = Pj.x - pix, dy = Pj.y - piy, dz = Pj.z - piz;
            float dd = fmaf(dx, dx, fmaf(dy, dy, dz * dz));
            float l  = sqrtf(dd);
            float linv = __fdividef(1.0f, l);   // inf on diagonal; handled below

            // dist_map uses the sq-formula (reference semantics)
            float pdot = fmaf(pix, Pj.x, fmaf(piy, Pj.y, piz * Pj.z));
            float d2f  = sqis + Pj.w - 2.0f * pdot;
            float dist = sqrtf(fmaxf(d2f, 0.0f));

            // rad[i,j] and rad[j,i]
            float doti = fmaf(nix, dx, fmaf(niy, dy, niz * dz));
            float ci   = __fdividef(doti, fmaf(nni, l, EPS));
            float radij = facos(fminf(fmaxf(ci, -1.0f), 1.0f));

            float dotj = -fmaf(Nj.x, dx, fmaf(Nj.y, dy, Nj.z * dz));
            float cj   = __fdividef(dotj, fmaf(Nj.w, l, EPS));
            float radji = facos(fminf(fmaxf(cj, -1.0f), 1.0f));

            float angle = fabsf(radij - radji);

            // seta
            float nnd = fmaf(nix, Nj.x, fmaf(niy, Nj.y, niz * Nj.z));
            float x   = nnd * rnni * rnn[j];
            float seta = facos(fminf(fmaxf(x, -1.0f), 1.0f));

            catRow[j * 3 + 0] = dist * 5.0f;
            catRow[j * 3 + 1] = seta;
            catRow[j * 3 + 2] = angle;

            // a_indices: atan2(|r x d|, r.d) == acos((r_hat . d) / |d|)  (Lagrange)
            float av[KNN];
            #pragma unroll
            for (int k = 0; k < KNN; k++) {
                float c = fmaf(rkx[k], dx, fmaf(rky[k], dy, rkz[k] * dz));
                av[k] = facos12(c * linv);
            }
            // diagonal: reference yields exactly 0 (XLA +0-init sum; arctan2(+0,+0)=0)
            if (j == i) {
                #pragma unroll
                for (int k = 0; k < KNN; k++) av[k] = 0.0f;
            }
            float4* ap = reinterpret_cast<float4*>(aRow + (size_t)j * KNN);
            ap[0] = make_float4(av[0], av[1], av[2], av[3]);
            ap[1] = make_float4(av[4], av[5], av[6], av[7]);
        }
        __syncthreads();  // dsel/rkv reused next row
    }
}

extern "C" void kernel_launch(void* const* d_in, const int* in_sizes, int n_in,
                              void* d_out, int out_size)
{
    const float* points  = (const float*)d_in[0];
    const float* normals = (const float*)d_in[1];
    (void)in_sizes; (void)n_in; (void)out_size;

    float* out  = (float*)d_out;
    float* cat  = out;                                   // [B,N,N,3]
    float* aidx = out + (size_t)BATCH * NPTS * NPTS * 3; // [B,N,N,K]

    gse_kernel<<<BATCH * (NPTS / TI), THREADS>>>(points, normals, cat, aidx);
}

// round 5
// speedup vs baseline: 2.1134x; 1.3159x over previous
#include <cuda_runtime.h>
#include <math_constants.h>

#define BATCH 2
#define NPTS 1024
#define KNN 8
#define TI 2
#define THREADS 256
#define NW (THREADS / 32)

// FACTOR_A = 180 / (15 * pi) = 12/pi
#define FACTOR_A 3.8197186342054885f
#define EPS 1e-6f

// Branchless acos, Abramowitz-Stegun 4.4.45 (|err| <= 6.7e-5 rad).
__device__ __forceinline__ float facos(float x) {
    float ax = fminf(fabsf(x), 1.0f);
    float p = fmaf(ax, -0.0187293f, 0.0742610f);
    p = fmaf(ax, p, -0.2121144f);
    p = fmaf(ax, p, 1.5707288f);
    float s = sqrtf(1.0f - ax) * p;
    return (x >= 0.0f) ? s : (CUDART_PI_F - s);
}

// FACTOR_A * acos(x); note pi * FACTOR_A == 12 exactly.
__device__ __forceinline__ float facos12(float x) {
    float ax = fminf(fabsf(x), 1.0f);
    float p = fmaf(ax, -0.0187293f * FACTOR_A, 0.0742610f * FACTOR_A);
    p = fmaf(ax, p, -0.2121144f * FACTOR_A);
    p = fmaf(ax, p, 1.5707288f * FACTOR_A);
    float s = sqrtf(1.0f - ax) * p;
    return (x >= 0.0f) ? s : (12.0f - s);
}

__global__ __launch_bounds__(THREADS)
void gse_kernel(const float* __restrict__ points,
                const float* __restrict__ normals,
                float* __restrict__ cat_out,   // [B,N,N,3]
                float* __restrict__ a_out)     // [B,N,N,K]
{
    __shared__ float4 P[NPTS];          // x, y, z, |p|^2 (strict rounding)
    __shared__ float4 Nn[NPTS];         // nx, ny, nz, |n|
    __shared__ float  rnn[NPTS];        // 1 / |n|
    __shared__ float  wval[NW * KNN];   // per-warp top-8 candidates
    __shared__ int    widx[NW * KNN];
    __shared__ int    knn_idx[KNN];
    __shared__ float  rkv[KNN][3];      // normalized ref vectors

    const int b    = blockIdx.x >> 9;            // N/TI = 512 blocks per batch
    const int i0   = (blockIdx.x & 511) * TI;
    const int tid  = threadIdx.x;
    const int lane = tid & 31;
    const int wid  = tid >> 5;

    // ---- load batch points/normals into smem ----
    const float* pb = points  + (size_t)b * NPTS * 3;
    const float* nb = normals + (size_t)b * NPTS * 3;
    for (int j = tid; j < NPTS; j += THREADS) {
        float x = pb[3 * j], y = pb[3 * j + 1], z = pb[3 * j + 2];
        // strict emulation of jnp.sum(p*p,-1): ((x*x)+(y*y))+(z*z), each rounded
        float sqs = __fadd_rn(__fadd_rn(__fmul_rn(x, x), __fmul_rn(y, y)),
                              __fmul_rn(z, z));
        P[j] = make_float4(x, y, z, sqs);
        float nx = nb[3 * j], ny = nb[3 * j + 1], nz = nb[3 * j + 2];
        float nn = sqrtf(nx * nx + ny * ny + nz * nz);
        Nn[j]  = make_float4(nx, ny, nz, nn);
        rnn[j] = __fdividef(1.0f, nn);
    }
    __syncthreads();

    for (int ii = 0; ii < TI; ii++) {
        const int i = i0 + ii;
        const float4 Pi = P[i];
        const float pix = Pi.x, piy = Pi.y, piz = Pi.z, sqis = Pi.w;

        // ---- phase A: strict fp32 selection distances, kept in registers ----
        float v[4]; int ix[4];
        #pragma unroll
        for (int s = 0; s < 4; s++) {
            int j = tid + s * THREADS;
            float4 Pj = P[j];
            float dot = __fadd_rn(__fadd_rn(__fmul_rn(pix, Pj.x),
                                            __fmul_rn(piy, Pj.y)),
                                  __fmul_rn(piz, Pj.z));
            float d2 = __fsub_rn(__fadd_rn(sqis, Pj.w), __fmul_rn(2.0f, dot));
            float dist = __fsqrt_rn(fmaxf(d2, 0.0f));
            v[s]  = (j == i) ? CUDART_INF_F : dist;  // drop self (== idx[...,0])
            ix[s] = j;
        }

        // ---- phase B1: per-warp top-8 via butterfly argmin, no barriers ----
        #pragma unroll
        for (int k = 0; k < KNN; k++) {
            float best = v[0]; int bi = ix[0]; int slot = 0;
            #pragma unroll
            for (int s = 1; s < 4; s++)
                if (v[s] < best || (v[s] == best && ix[s] < bi)) {
                    best = v[s]; bi = ix[s]; slot = s;
                }
            float rb = best; int ri = bi;
            #pragma unroll
            for (int off = 16; off > 0; off >>= 1) {
                float ov = __shfl_xor_sync(0xffffffffu, rb, off);
                int   oi = __shfl_xor_sync(0xffffffffu, ri, off);
                if (ov < rb || (ov == rb && oi < ri)) { rb = ov; ri = oi; }
            }
            if (ri == bi) v[slot] = CUDART_INF_F;  // indices unique -> one lane
            if (lane == 0) { wval[wid * KNN + k] = rb; widx[wid * KNN + k] = ri; }
        }
        __syncthreads();

        // ---- phase B2: warp 0 merges the 64 candidates ----
        if (wid == 0) {
            float m0 = wval[lane],  m1 = wval[lane + 32];
            int   j0 = widx[lane],  j1 = widx[lane + 32];
            #pragma unroll
            for (int k = 0; k < KNN; k++) {
                float best; int bi; int slot;
                if (m0 < m1 || (m0 == m1 && j0 < j1)) { best = m0; bi = j0; slot = 0; }
                else                                   { best = m1; bi = j1; slot = 1; }
                float rb = best; int ri = bi;
                #pragma unroll
                for (int off = 16; off > 0; off >>= 1) {
                    float ov = __shfl_xor_sync(0xffffffffu, rb, off);
                    int   oi = __shfl_xor_sync(0xffffffffu, ri, off);
                    if (ov < rb || (ov == rb && oi < ri)) { rb = ov; ri = oi; }
                }
                if (ri == bi) { if (slot == 0) m0 = CUDART_INF_F; else m1 = CUDART_INF_F; }
                if (lane == 0) knn_idx[k] = ri;
            }
        }
        __syncthreads();

        if (tid < KNN) {
            int jn = knn_idx[tid];
            float rx = P[jn].x - pix, ry = P[jn].y - piy, rz = P[jn].z - piz;
            float rinv = __fdividef(1.0f, sqrtf(rx * rx + ry * ry + rz * rz));
            rkv[tid][0] = rx * rinv;
            rkv[tid][1] = ry * rinv;
            rkv[tid][2] = rz * rinv;
        }
        __syncthreads();

        float rkx[KNN], rky[KNN], rkz[KNN];
        #pragma unroll
        for (int k = 0; k < KNN; k++) {
            rkx[k] = rkv[k][0];
            rky[k] = rkv[k][1];
            rkz[k] = rkv[k][2];
        }

        const float4 Ni = Nn[i];
        const float nix = Ni.x, niy = Ni.y, niz = Ni.z, nni = Ni.w;
        const float rnni = rnn[i];
        float* catRow = cat_out + ((size_t)(b * NPTS + i)) * NPTS * 3;
        float* aRow   = a_out   + ((size_t)(b * NPTS + i)) * NPTS * KNN;

        // ---- phase C: full pair row ----
        for (int j = tid; j < NPTS; j += THREADS) {
            float4 Pj = P[j];
            float4 Nj = Nn[j];
            float dx = Pj.x - pix, dy = Pj.y - piy, dz = Pj.z - piz;
            float dd = fmaf(dx, dx, fmaf(dy, dy, dz * dz));
            float l  = sqrtf(dd);
            float linv = __fdividef(1.0f, l);   // inf on diagonal; overwritten below

            // dist_map uses the sq-formula (reference semantics)
            float pdot = fmaf(pix, Pj.x, fmaf(piy, Pj.y, piz * Pj.z));
            float d2f  = sqis + Pj.w - 2.0f * pdot;
            float dist = sqrtf(fmaxf(d2f, 0.0f));

            // rad[i,j] and rad[j,i]
            float doti = fmaf(nix, dx, fmaf(niy, dy, niz * dz));
            float ci   = __fdividef(doti, fmaf(nni, l, EPS));
            float radij = facos(fminf(fmaxf(ci, -1.0f), 1.0f));

            float dotj = -fmaf(Nj.x, dx, fmaf(Nj.y, dy, Nj.z * dz));
            float cj   = __fdividef(dotj, fmaf(Nj.w, l, EPS));
            float radji = facos(fminf(fmaxf(cj, -1.0f), 1.0f));

            float angle = fabsf(radij - radji);

            // seta
            float nnd = fmaf(nix, Nj.x, fmaf(niy, Nj.y, niz * Nj.z));
            float x   = nnd * rnni * rnn[j];
            float seta = facos(fminf(fmaxf(x, -1.0f), 1.0f));

            catRow[j * 3 + 0] = dist * 5.0f;
            catRow[j * 3 + 1] = seta;
            catRow[j * 3 + 2] = angle;

            // a_indices: atan2(|r x d|, r.d) == acos((r_hat . d) / |d|)  (Lagrange)
            float av[KNN];
            #pragma unroll
            for (int k = 0; k < KNN; k++) {
                float c = fmaf(rkx[k], dx, fmaf(rky[k], dy, rkz[k] * dz));
                av[k] = facos12(c * linv);
            }
            // diagonal: reference yields exactly 0 (XLA +0-init sum; arctan2(+0,+0)=0)
            if (j == i) {
                #pragma unroll
                for (int k = 0; k < KNN; k++) av[k] = 0.0f;
            }
            float4* ap = reinterpret_cast<float4*>(aRow + (size_t)j * KNN);
            ap[0] = make_float4(av[0], av[1], av[2], av[3]);
            ap[1] = make_float4(av[4], av[5], av[6], av[7]);
        }
        __syncthreads();  // smem candidate arrays reused next row
    }
}

extern "C" void kernel_launch(void* const* d_in, const int* in_sizes, int n_in,
                              void* d_out, int out_size)
{
    const float* points  = (const float*)d_in[0];
    const float* normals = (const float*)d_in[1];
    (void)in_sizes; (void)n_in; (void)out_size;

    float* out  = (float*)d_out;
    float* cat  = out;                                   // [B,N,N,3]
    float* aidx = out + (size_t)BATCH * NPTS * NPTS * 3; // [B,N,N,K]

    gse_kernel<<<BATCH * (NPTS / TI), THREADS>>>(points, normals, cat, aidx);
}

// round 6
// speedup vs baseline: 2.4108x; 1.1407x over previous
#include <cuda_runtime.h>
#include <math_constants.h>

#define BATCH 2
#define NPTS 1024
#define KNN 8
#define TI 2
#define THREADS 256
#define NW (THREADS / 32)

// FACTOR_A = 180 / (15 * pi) = 12/pi
#define FACTOR_A 3.8197186342054885f
#define EPS 1e-6f

// Single-MUFU approximate sqrt (sqrt.approx.f32: ~2^-23 rel err, +0 -> +0).
__device__ __forceinline__ float fsqrt_fast(float x) {
    float r;
    asm("sqrt.approx.f32 %0, %1;" : "=f"(r) : "f"(x));
    return r;
}

// Branchless acos, Abramowitz-Stegun 4.4.45 (|err| <= 6.7e-5 rad).
// Internally clamps |x| to 1 and handles sign -> callers need no pre-clamp.
__device__ __forceinline__ float facos(float x) {
    float ax = fminf(fabsf(x), 1.0f);
    float p = fmaf(ax, -0.0187293f, 0.0742610f);
    p = fmaf(ax, p, -0.2121144f);
    p = fmaf(ax, p, 1.5707288f);
    float s = fsqrt_fast(1.0f - ax) * p;
    return (x >= 0.0f) ? s : (CUDART_PI_F - s);
}

// FACTOR_A * acos(x); note pi * FACTOR_A == 12 exactly.
__device__ __forceinline__ float facos12(float x) {
    float ax = fminf(fabsf(x), 1.0f);
    float p = fmaf(ax, -0.0187293f * FACTOR_A, 0.0742610f * FACTOR_A);
    p = fmaf(ax, p, -0.2121144f * FACTOR_A);
    p = fmaf(ax, p, 1.5707288f * FACTOR_A);
    float s = fsqrt_fast(1.0f - ax) * p;
    return (x >= 0.0f) ? s : (12.0f - s);
}

__global__ __launch_bounds__(THREADS)
void gse_kernel(const float* __restrict__ points,
                const float* __restrict__ normals,
                float* __restrict__ cat_out,   // [B,N,N,3]
                float* __restrict__ a_out)     // [B,N,N,K]
{
    __shared__ float4 P[NPTS];          // x, y, z, |p|^2 (strict rounding)
    __shared__ float4 Nn[NPTS];         // nx, ny, nz, |n|
    __shared__ float  rnn[NPTS];        // 1 / |n|
    __shared__ float  wval[NW * KNN];   // per-warp top-8 candidates
    __shared__ int    widx[NW * KNN];
    __shared__ int    knn_idx[KNN];
    __shared__ float  rkv[KNN][3];      // normalized ref vectors

    const int b    = blockIdx.x >> 9;            // N/TI = 512 blocks per batch
    const int i0   = (blockIdx.x & 511) * TI;
    const int tid  = threadIdx.x;
    const int lane = tid & 31;
    const int wid  = tid >> 5;

    // ---- load batch points/normals into smem ----
    const float* pb = points  + (size_t)b * NPTS * 3;
    const float* nb = normals + (size_t)b * NPTS * 3;
    for (int j = tid; j < NPTS; j += THREADS) {
        float x = pb[3 * j], y = pb[3 * j + 1], z = pb[3 * j + 2];
        // strict emulation of jnp.sum(p*p,-1): ((x*x)+(y*y))+(z*z), each rounded
        float sqs = __fadd_rn(__fadd_rn(__fmul_rn(x, x), __fmul_rn(y, y)),
                              __fmul_rn(z, z));
        P[j] = make_float4(x, y, z, sqs);
        float nx = nb[3 * j], ny = nb[3 * j + 1], nz = nb[3 * j + 2];
        float nn = sqrtf(nx * nx + ny * ny + nz * nz);
        Nn[j]  = make_float4(nx, ny, nz, nn);
        rnn[j] = __fdividef(1.0f, nn);
    }
    __syncthreads();

    for (int ii = 0; ii < TI; ii++) {
        const int i = i0 + ii;
        const float4 Pi = P[i];
        const float pix = Pi.x, piy = Pi.y, piz = Pi.z, sqis = Pi.w;

        // ---- phase A: strict fp32 selection distances, kept in registers ----
        // (IEEE ops only; must stay bit-exact vs the jax reference for ordering)
        float v[4]; int ix[4];
        #pragma unroll
        for (int s = 0; s < 4; s++) {
            int j = tid + s * THREADS;
            float4 Pj = P[j];
            float dot = __fadd_rn(__fadd_rn(__fmul_rn(pix, Pj.x),
                                            __fmul_rn(piy, Pj.y)),
                                  __fmul_rn(piz, Pj.z));
            float d2 = __fsub_rn(__fadd_rn(sqis, Pj.w), __fmul_rn(2.0f, dot));
            float dist = __fsqrt_rn(fmaxf(d2, 0.0f));
            v[s]  = (j == i) ? CUDART_INF_F : dist;  // drop self (== idx[...,0])
            ix[s] = j;
        }

        // ---- phase B1: per-warp top-8 via butterfly argmin, no barriers ----
        #pragma unroll
        for (int k = 0; k < KNN; k++) {
            float best = v[0]; int bi = ix[0]; int slot = 0;
            #pragma unroll
            for (int s = 1; s < 4; s++)
                if (v[s] < best || (v[s] == best && ix[s] < bi)) {
                    best = v[s]; bi = ix[s]; slot = s;
                }
            float rb = best; int ri = bi;
            #pragma unroll
            for (int off = 16; off > 0; off >>= 1) {
                float ov = __shfl_xor_sync(0xffffffffu, rb, off);
                int   oi = __shfl_xor_sync(0xffffffffu, ri, off);
                if (ov < rb || (ov == rb && oi < ri)) { rb = ov; ri = oi; }
            }
            if (ri == bi) v[slot] = CUDART_INF_F;  // indices unique -> one lane
            if (lane == 0) { wval[wid * KNN + k] = rb; widx[wid * KNN + k] = ri; }
        }
        __syncthreads();

        // ---- phase B2: warp 0 merges the 64 candidates ----
        if (wid == 0) {
            float m0 = wval[lane],  m1 = wval[lane + 32];
            int   j0 = widx[lane],  j1 = widx[lane + 32];
            #pragma unroll
            for (int k = 0; k < KNN; k++) {
                float best; int bi; int slot;
                if (m0 < m1 || (m0 == m1 && j0 < j1)) { best = m0; bi = j0; slot = 0; }
                else                                   { best = m1; bi = j1; slot = 1; }
                float rb = best; int ri = bi;
                #pragma unroll
                for (int off = 16; off > 0; off >>= 1) {
                    float ov = __shfl_xor_sync(0xffffffffu, rb, off);
                    int   oi = __shfl_xor_sync(0xffffffffu, ri, off);
                    if (ov < rb || (ov == rb && oi < ri)) { rb = ov; ri = oi; }
                }
                if (ri == bi) { if (slot == 0) m0 = CUDART_INF_F; else m1 = CUDART_INF_F; }
                if (lane == 0) knn_idx[k] = ri;
            }
        }
        __syncthreads();

        if (tid < KNN) {
            int jn = knn_idx[tid];
            float rx = P[jn].x - pix, ry = P[jn].y - piy, rz = P[jn].z - piz;
            float rinv = __fdividef(1.0f, sqrtf(rx * rx + ry * ry + rz * rz));
            rkv[tid][0] = rx * rinv;
            rkv[tid][1] = ry * rinv;
            rkv[tid][2] = rz * rinv;
        }
        __syncthreads();

        float rkx[KNN], rky[KNN], rkz[KNN];
        #pragma unroll
        for (int k = 0; k < KNN; k++) {
            rkx[k] = rkv[k][0];
            rky[k] = rkv[k][1];
            rkz[k] = rkv[k][2];
        }

        const float4 Ni = Nn[i];
        const float nix = Ni.x, niy = Ni.y, niz = Ni.z, nni = Ni.w;
        const float rnni = rnn[i];
        float* catRow = cat_out + ((size_t)(b * NPTS + i)) * NPTS * 3;
        float* aRow   = a_out   + ((size_t)(b * NPTS + i)) * NPTS * KNN;

        // ---- phase C: full pair row ----
        for (int j = tid; j < NPTS; j += THREADS) {
            float4 Pj = P[j];
            float4 Nj = Nn[j];
            float dx = Pj.x - pix, dy = Pj.y - piy, dz = Pj.z - piz;
            float dd = fmaf(dx, dx, fmaf(dy, dy, dz * dz));
            float l  = fsqrt_fast(dd);              // +0 on diagonal
            float linv = __fdividef(1.0f, l);       // inf on diagonal; av overridden

            // dist_map uses the sq-formula (reference semantics)
            float pdot = fmaf(pix, Pj.x, fmaf(piy, Pj.y, piz * Pj.z));
            float d2f  = sqis + Pj.w - 2.0f * pdot;
            float dist = fsqrt_fast(fmaxf(d2f, 0.0f));

            // rad[i,j] and rad[j,i]  (facos clamps internally)
            float doti = fmaf(nix, dx, fmaf(niy, dy, niz * dz));
            float radij = facos(__fdividef(doti, fmaf(nni, l, EPS)));

            float dotj = -fmaf(Nj.x, dx, fmaf(Nj.y, dy, Nj.z * dz));
            float radji = facos(__fdividef(dotj, fmaf(Nj.w, l, EPS)));

            float angle = fabsf(radij - radji);

            // seta
            float nnd = fmaf(nix, Nj.x, fmaf(niy, Nj.y, niz * Nj.z));
            float x   = nnd * rnni * rnn[j];
            if (x != x) x = 0.0f;                   // NaN -> 0 (reference where)
            float seta = facos(x);

            catRow[j * 3 + 0] = dist * 5.0f;
            catRow[j * 3 + 1] = seta;
            catRow[j * 3 + 2] = angle;

            // a_indices: atan2(|r x d|, r.d) == acos((r_hat . d) / |d|)  (Lagrange)
            float av[KNN];
            #pragma unroll
            for (int k = 0; k < KNN; k++) {
                float c = fmaf(rkx[k], dx, fmaf(rky[k], dy, rkz[k] * dz));
                av[k] = facos12(c * linv);
            }
            // diagonal: reference yields exactly 0 (XLA +0-init sum; arctan2(+0,+0)=0)
            if (j == i) {
                #pragma unroll
                for (int k = 0; k < KNN; k++) av[k] = 0.0f;
            }
            float4* ap = reinterpret_cast<float4*>(aRow + (size_t)j * KNN);
            ap[0] = make_float4(av[0], av[1], av[2], av[3]);
            ap[1] = make_float4(av[4], av[5], av[6], av[7]);
        }
        __syncthreads();  // smem candidate arrays reused next row
    }
}

extern "C" void kernel_launch(void* const* d_in, const int* in_sizes, int n_in,
                              void* d_out, int out_size)
{
    const float* points  = (const float*)d_in[0];
    const float* normals = (const float*)d_in[1];
    (void)in_sizes; (void)n_in; (void)out_size;

    float* out  = (float*)d_out;
    float* cat  = out;                                   // [B,N,N,3]
    float* aidx = out + (size_t)BATCH * NPTS * NPTS * 3; // [B,N,N,K]

    gse_kernel<<<BATCH * (NPTS / TI), THREADS>>>(points, normals, cat, aidx);
}

// round 7
// speedup vs baseline: 3.3125x; 1.3740x over previous
#include <cuda_runtime.h>
#include <math_constants.h>

#define BATCH 2
#define NPTS 1024
#define KNN 8
#define TI 2
#define THREADS 256
#define NW (THREADS / 32)

// FACTOR_A = 180 / (15 * pi) = 12/pi
#define FACTOR_A 3.8197186342054885f
#define EPS 1e-6f

// Single-MUFU approximate sqrt (sqrt.approx.f32: ~2^-23 rel err, +0 -> +0).
__device__ __forceinline__ float fsqrt_fast(float x) {
    float r;
    asm("sqrt.approx.f32 %0, %1;" : "=f"(r) : "f"(x));
    return r;
}

// Branchless acos, Abramowitz-Stegun 4.4.45 (|err| <= 6.7e-5 rad).
// Internally clamps |x| to 1 and handles sign -> callers need no pre-clamp.
__device__ __forceinline__ float facos(float x) {
    float ax = fminf(fabsf(x), 1.0f);
    float p = fmaf(ax, -0.0187293f, 0.0742610f);
    p = fmaf(ax, p, -0.2121144f);
    p = fmaf(ax, p, 1.5707288f);
    float s = fsqrt_fast(1.0f - ax) * p;
    return (x >= 0.0f) ? s : (CUDART_PI_F - s);
}

// FACTOR_A * acos(x); note pi * FACTOR_A == 12 exactly.
__device__ __forceinline__ float facos12(float x) {
    float ax = fminf(fabsf(x), 1.0f);
    float p = fmaf(ax, -0.0187293f * FACTOR_A, 0.0742610f * FACTOR_A);
    p = fmaf(ax, p, -0.2121144f * FACTOR_A);
    p = fmaf(ax, p, 1.5707288f * FACTOR_A);
    float s = fsqrt_fast(1.0f - ax) * p;
    return (x >= 0.0f) ? s : (12.0f - s);
}

__global__ __launch_bounds__(THREADS)
void gse_kernel(const float* __restrict__ points,
                const float* __restrict__ normals,
                float* __restrict__ cat_out,   // [B,N,N,3]
                float* __restrict__ a_out)     // [B,N,N,K]
{
    __shared__ float4   P[NPTS];          // x, y, z, |p|^2 (strict rounding)
    __shared__ float4   Nn[NPTS];         // nx, ny, nz, |n|
    __shared__ float    rnn[NPTS];        // 1 / |n|
    __shared__ unsigned wval[NW * KNN];   // per-warp top-8 candidate dist-bits
    __shared__ unsigned widx[NW * KNN];   // ... and their indices
    __shared__ int      knn_idx[KNN];
    __shared__ float    rkv[KNN][3];      // normalized ref vectors

    const int b    = blockIdx.x >> 9;            // N/TI = 512 blocks per batch
    const int i0   = (blockIdx.x & 511) * TI;
    const int tid  = threadIdx.x;
    const int lane = tid & 31;
    const int wid  = tid >> 5;

    // ---- load batch points/normals into smem ----
    const float* pb = points  + (size_t)b * NPTS * 3;
    const float* nb = normals + (size_t)b * NPTS * 3;
    for (int j = tid; j < NPTS; j += THREADS) {
        float x = pb[3 * j], y = pb[3 * j + 1], z = pb[3 * j + 2];
        // strict emulation of jnp.sum(p*p,-1): ((x*x)+(y*y))+(z*z), each rounded
        float sqs = __fadd_rn(__fadd_rn(__fmul_rn(x, x), __fmul_rn(y, y)),
                              __fmul_rn(z, z));
        P[j] = make_float4(x, y, z, sqs);
        float nx = nb[3 * j], ny = nb[3 * j + 1], nz = nb[3 * j + 2];
        float nn = sqrtf(nx * nx + ny * ny + nz * nz);
        Nn[j]  = make_float4(nx, ny, nz, nn);
        rnn[j] = __fdividef(1.0f, nn);
    }
    __syncthreads();

    for (int ii = 0; ii < TI; ii++) {
        const int i = i0 + ii;
        const float4 Pi = P[i];
        const float pix = Pi.x, piy = Pi.y, piz = Pi.z, sqis = Pi.w;

        // ---- phase A: strict fp32 selection distances, kept in registers ----
        // (IEEE ops only; must stay bit-exact vs the jax reference for ordering)
        float v[4]; int ix[4];
        #pragma unroll
        for (int s = 0; s < 4; s++) {
            int j = tid + s * THREADS;
            float4 Pj = P[j];
            float dot = __fadd_rn(__fadd_rn(__fmul_rn(pix, Pj.x),
                                            __fmul_rn(piy, Pj.y)),
                                  __fmul_rn(piz, Pj.z));
            float d2 = __fsub_rn(__fadd_rn(sqis, Pj.w), __fmul_rn(2.0f, dot));
            float dist = __fsqrt_rn(fmaxf(d2, 0.0f));
            v[s]  = (j == i) ? CUDART_INF_F : dist;  // drop self (== idx[...,0])
            ix[s] = j;
        }

        // ---- phase B1: sort-4 then redux-based top-8 extraction ----
        // exact lexicographic (v, idx) order; indices globally unique
        #define CSWAP(a, bb)                                                  \
            {                                                                 \
                bool sw = (v[bb] < v[a]) ||                                   \
                          (v[bb] == v[a] && ix[bb] < ix[a]);                  \
                float tv = sw ? v[bb] : v[a];                                 \
                v[bb] = sw ? v[a] : v[bb];  v[a] = tv;                        \
                int ti = sw ? ix[bb] : ix[a];                                 \
                ix[bb] = sw ? ix[a] : ix[bb]; ix[a] = ti;                     \
            }
        CSWAP(0, 1) CSWAP(2, 3) CSWAP(0, 2) CSWAP(1, 3) CSWAP(1, 2)
        #undef CSWAP

        #pragma unroll
        for (int k = 0; k < KNN; k++) {
            unsigned fb   = __float_as_uint(v[0]);     // nonneg -> bits monotonic
            unsigned minb = __reduce_min_sync(0xffffffffu, fb);
            unsigned cand = (fb == minb) ? (unsigned)ix[0] : 0xffffffffu;
            unsigned wmin = __reduce_min_sync(0xffffffffu, cand);
            if (fb == minb && (unsigned)ix[0] == wmin) {   // unique winner pops
                v[0] = v[1]; ix[0] = ix[1];
                v[1] = v[2]; ix[1] = ix[2];
                v[2] = v[3]; ix[2] = ix[3];
                v[3] = CUDART_INF_F;
            }
            if (lane == 0) { wval[wid * KNN + k] = minb; widx[wid * KNN + k] = wmin; }
        }
        __syncthreads();

        // ---- phase B2: warp 0 merges the 64 candidates (same redux scheme) ----
        if (wid == 0) {
            unsigned mv0 = wval[lane],  mv1 = wval[lane + 32];
            unsigned id0 = widx[lane],  id1 = widx[lane + 32];
            #pragma unroll
            for (int k = 0; k < KNN; k++) {
                bool sel1 = (mv1 < mv0) || (mv1 == mv0 && id1 < id0);
                unsigned fv = sel1 ? mv1 : mv0;
                unsigned fi = sel1 ? id1 : id0;
                unsigned minb = __reduce_min_sync(0xffffffffu, fv);
                unsigned cand = (fv == minb) ? fi : 0xffffffffu;
                unsigned wmin = __reduce_min_sync(0xffffffffu, cand);
                if (fv == minb && fi == wmin) {
                    if (sel1) mv1 = 0xffffffffu; else mv0 = 0xffffffffu;
                }
                if (lane == 0) knn_idx[k] = (int)wmin;
            }
        }
        __syncthreads();

        if (tid < KNN) {
            int jn = knn_idx[tid];
            float rx = P[jn].x - pix, ry = P[jn].y - piy, rz = P[jn].z - piz;
            float rinv = __fdividef(1.0f, sqrtf(rx * rx + ry * ry + rz * rz));
            rkv[tid][0] = rx * rinv;
            rkv[tid][1] = ry * rinv;
            rkv[tid][2] = rz * rinv;
        }
        __syncthreads();

        float rkx[KNN], rky[KNN], rkz[KNN];
        #pragma unroll
        for (int k = 0; k < KNN; k++) {
            rkx[k] = rkv[k][0];
            rky[k] = rkv[k][1];
            rkz[k] = rkv[k][2];
        }

        const float4 Ni = Nn[i];
        const float nix = Ni.x, niy = Ni.y, niz = Ni.z, nni = Ni.w;
        const float rnni = rnn[i];
        float* catRow = cat_out + ((size_t)(b * NPTS + i)) * NPTS * 3;
        float* aRow   = a_out   + ((size_t)(b * NPTS + i)) * NPTS * KNN;

        // ---- phase C: full pair row ----
        for (int j = tid; j < NPTS; j += THREADS) {
            float4 Pj = P[j];
            float4 Nj = Nn[j];
            float dx = Pj.x - pix, dy = Pj.y - piy, dz = Pj.z - piz;
            float dd = fmaf(dx, dx, fmaf(dy, dy, dz * dz));
            float l  = fsqrt_fast(dd);              // +0 on diagonal
            float linv = __fdividef(1.0f, l);       // inf on diagonal; av overridden

            // dist_map uses the sq-formula (reference semantics)
            float pdot = fmaf(pix, Pj.x, fmaf(piy, Pj.y, piz * Pj.z));
            float d2f  = sqis + Pj.w - 2.0f * pdot;
            float dist = fsqrt_fast(fmaxf(d2f, 0.0f));

            // rad[i,j] and rad[j,i]  (facos clamps internally)
            float doti = fmaf(nix, dx, fmaf(niy, dy, niz * dz));
            float radij = facos(__fdividef(doti, fmaf(nni, l, EPS)));

            float dotj = -fmaf(Nj.x, dx, fmaf(Nj.y, dy, Nj.z * dz));
            float radji = facos(__fdividef(dotj, fmaf(Nj.w, l, EPS)));

            float angle = fabsf(radij - radji);

            // seta
            float nnd = fmaf(nix, Nj.x, fmaf(niy, Nj.y, niz * Nj.z));
            float x   = nnd * rnni * rnn[j];
            if (x != x) x = 0.0f;                   // NaN -> 0 (reference where)
            float seta = facos(x);

            catRow[j * 3 + 0] = dist * 5.0f;
            catRow[j * 3 + 1] = seta;
            catRow[j * 3 + 2] = angle;

            // a_indices: atan2(|r x d|, r.d) == acos((r_hat . d) / |d|)  (Lagrange)
            float av[KNN];
            #pragma unroll
            for (int k = 0; k < KNN; k++) {
                float c = fmaf(rkx[k], dx, fmaf(rky[k], dy, rkz[k] * dz));
                av[k] = facos12(c * linv);
            }
            // diagonal: reference yields exactly 0 (XLA +0-init sum; arctan2(+0,+0)=0)
            if (j == i) {
                #pragma unroll
                for (int k = 0; k < KNN; k++) av[k] = 0.0f;
            }
            float4* ap = reinterpret_cast<float4*>(aRow + (size_t)j * KNN);
            ap[0] = make_float4(av[0], av[1], av[2], av[3]);
            ap[1] = make_float4(av[4], av[5], av[6], av[7]);
        }
        __syncthreads();  // smem candidate arrays reused next row
    }
}

extern "C" void kernel_launch(void* const* d_in, const int* in_sizes, int n_in,
                              void* d_out, int out_size)
{
    const float* points  = (const float*)d_in[0];
    const float* normals = (const float*)d_in[1];
    (void)in_sizes; (void)n_in; (void)out_size;

    float* out  = (float*)d_out;
    float* cat  = out;                                   // [B,N,N,3]
    float* aidx = out + (size_t)BATCH * NPTS * NPTS * 3; // [B,N,N,K]

    gse_kernel<<<BATCH * (NPTS / TI), THREADS>>>(points, normals, cat, aidx);
}